// round 7
// baseline (speedup 1.0000x reference)
#include <cuda_runtime.h>
#include <cuda_bf16.h>
#include <math.h>
#include <stdint.h>

#define VOCABN 50000
#define EMBN   300
#define KPAD   320     // EMB padded to 10 chunks of 32
#define TLEN   256
#define HIDN   512
#define G4     2048    // 4*HID
#define NCLSN  10
#define BATCHN 64
#define MROWS  (TLEN*BATCHN)

// ---------------------------------------------------------------------------
// Device scratch
// ---------------------------------------------------------------------------
__device__ __align__(256) float g_xz[2][TLEN][BATCHN][G4]; // permuted gate cols
__device__ __align__(256) float g_h[2][2][BATCHN][HIDN];   // fp32 h (final step, for dense)
__device__ __align__(256) unsigned g_barc[2];              // per-dir barrier counters

__device__ __align__(256) __nv_bfloat16 g_Ahi[(size_t)MROWS * KPAD];
__device__ __align__(256) __nv_bfloat16 g_Alo[(size_t)MROWS * KPAD];
__device__ __align__(256) __nv_bfloat16 g_Bhi[(size_t)2 * G4 * KPAD];
__device__ __align__(256) __nv_bfloat16 g_Blo[(size_t)2 * G4 * KPAD];
__device__ __align__(256) float g_biasp[2 * G4];

// recurrence operands: h as bf16 hi/lo planes, Wh^T (permuted) as bf16 hi/lo
__device__ __align__(256) __nv_bfloat16 g_hb[2][2][2][BATCHN][HIDN];   // [dir][pp][plane][b][k]
__device__ __align__(256) __nv_bfloat16 g_WhT[2][2][G4][HIDN];         // [dir][plane][p][k]

__device__ __forceinline__ int perm_src(int p) {
    return ((p >> 3) & 3) * HIDN + (p >> 5) * 8 + (p & 7);
}

__device__ __forceinline__ uint32_t smem_to_u32(const void* p) {
    uint32_t a;
    asm("{ .reg .u64 t; cvta.to.shared.u64 t, %1; cvt.u32.u64 %0, t; }"
        : "=r"(a) : "l"(p));
    return a;
}

// ---------------------------------------------------------------------------
// mma.sync / ldmatrix / cp.async helpers (baseline PTX, no 'a' features)
// ---------------------------------------------------------------------------
#define LDSM_X4(r0, r1, r2, r3, addr) \
    asm volatile("ldmatrix.sync.aligned.m8n8.x4.shared.b16 {%0,%1,%2,%3}, [%4];" \
        : "=r"(r0), "=r"(r1), "=r"(r2), "=r"(r3) : "r"(addr))

#define MMA_BF16(c, a, b) \
    asm volatile("mma.sync.aligned.m16n8k16.row.col.f32.bf16.bf16.f32 " \
        "{%0,%1,%2,%3}, {%4,%5,%6,%7}, {%8,%9}, {%0,%1,%2,%3};" \
        : "+f"((c)[0]), "+f"((c)[1]), "+f"((c)[2]), "+f"((c)[3]) \
        : "r"((a)[0]), "r"((a)[1]), "r"((a)[2]), "r"((a)[3]), \
          "r"((b)[0]), "r"((b)[1]))

#define CP_ASYNC16(dst, src) \
    asm volatile("cp.async.cg.shared.global [%0], [%1], 16;" \
        :: "r"(dst), "l"(src) : "memory")
#define CP_COMMIT() asm volatile("cp.async.commit_group;" ::: "memory")
#define CP_WAITG(n) asm volatile("cp.async.wait_group %0;" :: "n"(n) : "memory")

// swizzle of a 16B-chunk index within a 1KB row (XOR low 3 bits with row&7)
__device__ __forceinline__ uint32_t swz16(uint32_t c16, uint32_t row) {
    return (c16 & ~7u) | ((c16 ^ row) & 7u);
}

__device__ __forceinline__ float fsig(float x) {
    return __fdividef(1.f, 1.f + __expf(-x));
}

// ---------------------------------------------------------------------------
// Prep kernels
// ---------------------------------------------------------------------------
__global__ __launch_bounds__(KPAD) void prep_w(
    const float* __restrict__ Wx_f, const float* __restrict__ b_f,
    const float* __restrict__ Wx_b, const float* __restrict__ b_b)
{
    int n = blockIdx.x, dir = blockIdx.y, k = threadIdx.x;
    if (n == 0 && dir == 0 && k < 2) g_barc[k] = 0u;   // barrier reset
    int src = perm_src(n);
    const float* Wx = dir ? Wx_b : Wx_f;
    float v = (k < EMBN) ? Wx[(size_t)k * G4 + src] : 0.f;
    __nv_bfloat16 hi = __float2bfloat16(v);
    __nv_bfloat16 lo = __float2bfloat16(v - __bfloat162float(hi));
    size_t idx = (size_t)(dir * G4 + n) * KPAD + k;
    g_Bhi[idx] = hi;
    g_Blo[idx] = lo;
    if (k == 0) g_biasp[dir * G4 + n] = (dir ? b_b : b_f)[src];
}

__global__ __launch_bounds__(KPAD) void prep_a(
    const int* __restrict__ x, const float* __restrict__ emb)
{
    int row = blockIdx.x;
    int t = row >> 6, b = row & 63;
    __shared__ int tok;
    if (threadIdx.x == 0) tok = x[b * TLEN + t];
    __syncthreads();
    int k = threadIdx.x;
    float v = (k < EMBN) ? emb[(size_t)tok * EMBN + k] : 0.f;
    __nv_bfloat16 hi = __float2bfloat16(v);
    __nv_bfloat16 lo = __float2bfloat16(v - __bfloat162float(hi));
    size_t idx = (size_t)row * KPAD + k;
    g_Ahi[idx] = hi;
    g_Alo[idx] = lo;
}

// Wh^T with gate-column permutation, bf16 hi/lo planes, k-contiguous rows
__global__ __launch_bounds__(HIDN) void prep_wh(
    const float* __restrict__ Wh_f, const float* __restrict__ Wh_b)
{
    int p = blockIdx.x, dir = blockIdx.y, k = threadIdx.x;
    int src = perm_src(p);
    float v = (dir ? Wh_b : Wh_f)[(size_t)k * G4 + src];
    __nv_bfloat16 hi = __float2bfloat16(v);
    __nv_bfloat16 lo = __float2bfloat16(v - __bfloat162float(hi));
    g_WhT[dir][0][p][k] = hi;
    g_WhT[dir][1][p][k] = lo;
}

// ---------------------------------------------------------------------------
// Tensor-core (mma.sync bf16x3) input projection. Change vs R4: minBlocks=2
// (caps regs at 128 so 2 CTAs/SM are resident; was 134 regs -> 1 CTA/SM).
// ---------------------------------------------------------------------------
#define GT_STAGE 32768
#define GT_SMEM  (2 * GT_STAGE)
#define NCHUNK   10

__global__ __launch_bounds__(256, 2) void gemm_mma()
{
    extern __shared__ char sm[];
    const uint32_t smb = smem_to_u32(sm);
    const int tid = threadIdx.x, wid = tid >> 5, lane = tid & 31;

    const int ntile = blockIdx.x & 15;
    const int mtile = (blockIdx.x >> 4) & 127;
    const int dir   = blockIdx.x >> 11;
    const int m0 = mtile * 128, n0 = ntile * 128;

    const int mwarp = (wid >> 2) * 64;
    const int nwarp = (wid & 3) * 32;

    const int crow = tid >> 3;
    const int cc   = tid & 7;
    const __nv_bfloat16* srcA_base = (cc < 4) ? g_Ahi : g_Alo;
    const __nv_bfloat16* srcB_base = (cc < 4) ? g_Bhi : g_Blo;
    const int ksub = (cc & 3) * 8;

    const int a_row = (lane & 7) + ((lane >> 3) & 1) * 8;
    const int a_cad = (lane >> 4) & 1;
    const int b_row = (lane & 7) + ((lane >> 4) & 1) * 8;
    const int b_cad = (lane >> 3) & 1;

    float c[4][4][4];
    #pragma unroll
    for (int i = 0; i < 4; i++)
        #pragma unroll
        for (int j = 0; j < 4; j++)
            #pragma unroll
            for (int e = 0; e < 4; e++) c[i][j][e] = 0.f;

    #define ISSUE_COPY(kc, stage) do {                                         \
        uint32_t sA = smb + (stage) * GT_STAGE;                                \
        uint32_t sB = sA + 16384;                                              \
        _Pragma("unroll")                                                      \
        for (int q = 0; q < 4; q++) {                                          \
            int row = crow + q * 32;                                           \
            uint32_t dof = (uint32_t)row * 128 + ((cc ^ (row & 7)) * 16);      \
            const __nv_bfloat16* sa = srcA_base +                              \
                (size_t)(m0 + row) * KPAD + (kc) * 32 + ksub;                  \
            const __nv_bfloat16* sb = srcB_base +                              \
                (size_t)(dir * G4 + n0 + row) * KPAD + (kc) * 32 + ksub;       \
            CP_ASYNC16(sA + dof, sa);                                          \
            CP_ASYNC16(sB + dof, sb);                                          \
        }                                                                      \
        CP_COMMIT();                                                           \
    } while (0)

    ISSUE_COPY(0, 0);

    #pragma unroll 1
    for (int kc = 0; kc < NCHUNK; kc++) {
        if (kc + 1 < NCHUNK) {
            ISSUE_COPY(kc + 1, (kc + 1) & 1);
            CP_WAITG(1);
        } else {
            CP_WAITG(0);
        }
        __syncthreads();

        const uint32_t sA = smb + (kc & 1) * GT_STAGE;
        const uint32_t sB = sA + 16384;

        #pragma unroll
        for (int ks = 0; ks < 2; ks++) {
            uint32_t ah[4][4], al[4][4], bh[4][2], bl[4][2];
            #pragma unroll
            for (int mt = 0; mt < 4; mt++) {
                int row = mwarp + mt * 16 + a_row;
                int swzr = row & 7;
                uint32_t oh = sA + (uint32_t)row * 128 +
                              (((ks * 2 + a_cad)     ^ swzr) * 16);
                uint32_t ol = sA + (uint32_t)row * 128 +
                              (((4 + ks * 2 + a_cad) ^ swzr) * 16);
                LDSM_X4(ah[mt][0], ah[mt][1], ah[mt][2], ah[mt][3], oh);
                LDSM_X4(al[mt][0], al[mt][1], al[mt][2], al[mt][3], ol);
            }
            #pragma unroll
            for (int j = 0; j < 2; j++) {
                int row = nwarp + j * 16 + b_row;
                int swzr = row & 7;
                uint32_t oh = sB + (uint32_t)row * 128 +
                              (((ks * 2 + b_cad)     ^ swzr) * 16);
                uint32_t ol = sB + (uint32_t)row * 128 +
                              (((4 + ks * 2 + b_cad) ^ swzr) * 16);
                LDSM_X4(bh[2*j][0], bh[2*j][1], bh[2*j+1][0], bh[2*j+1][1], oh);
                LDSM_X4(bl[2*j][0], bl[2*j][1], bl[2*j+1][0], bl[2*j+1][1], ol);
            }
            #pragma unroll
            for (int mt = 0; mt < 4; mt++)
                #pragma unroll
                for (int nt = 0; nt < 4; nt++) {
                    MMA_BF16(c[mt][nt], ah[mt], bh[nt]);
                    MMA_BF16(c[mt][nt], ah[mt], bl[nt]);
                    MMA_BF16(c[mt][nt], al[mt], bh[nt]);
                }
        }
        __syncthreads();
    }

    const int qrow = lane >> 2;
    const int qcol = (lane & 3) * 2;
    #pragma unroll
    for (int nt = 0; nt < 4; nt++) {
        int coll = nwarp + nt * 8 + qcol;
        int col  = n0 + coll;
        float2 bv = *(const float2*)&g_biasp[dir * G4 + col];
        #pragma unroll
        for (int mt = 0; mt < 4; mt++) {
            #pragma unroll
            for (int half = 0; half < 2; half++) {
                int g = m0 + mwarp + mt * 16 + qrow + half * 8;
                int t = g >> 6, b = g & 63;
                int tout = dir ? (TLEN - 1 - t) : t;
                float2 v;
                v.x = c[mt][nt][half * 2 + 0] + bv.x;
                v.y = c[mt][nt][half * 2 + 1] + bv.y;
                *(float2*)&g_xz[dir][tout][b][col] = v;
            }
        }
    }
}

// ---------------------------------------------------------------------------
// Kernel 2: persistent bidirectional LSTM recurrence, mma.sync bf16x3.
// 8 warps = 2(M:32 rows) x 4(K:128). NEW vs R4:
//  - gates + cell state fully register-resident in kq0 warps (fragment cols
//    nt=0..3 are exactly gates i/f/g/o for units qcol,qcol+1) -> no zs/cs smem
//  - 3-buffer single-round K reduction (3 syncthreads per step, was 5)
//  - staging in 4 commit groups, MMA interleaved with wait_group 3/2/1/0
//  - __expf-based sigmoid
// ---------------------------------------------------------------------------
#define LS_A     0                   // A planes: 2 x 64KB (rows b, 1KB each)
#define LS_B     131072              // B planes: 2 x 32KB (rows n, 1KB each)
#define LS_SPILL 196608              // 3 bufs x [64][34] fp32 = 3 x 8704
#define LSTM_SMEM_BYTES (196608 + 3 * 8704)   // 222720

__global__ __launch_bounds__(256, 1) void lstm_kernel()
{
    extern __shared__ char sm[];
    const uint32_t smb = smem_to_u32(sm);

    const int tid   = threadIdx.x;
    const int wid   = tid >> 5, lane = tid & 31;
    const int dir   = blockIdx.x >> 6;
    const int slice = blockIdx.x & 63;

    const int mhalf = wid & 1;        // M half: rows mhalf*32..+31
    const int kq    = wid >> 1;       // K quarter: k kq*128..+127

    // ---- one-time: load Wh^T slice (hi/lo) into smem ----
    #pragma unroll
    for (int i = tid; i < 4096; i += 256) {       // 4096 16B chunks
        int plane = i >> 11;
        int row   = (i >> 6) & 31;
        int c16   = i & 63;
        const __nv_bfloat16* src = &g_WhT[dir][plane][slice * 32 + row][c16 * 8];
        uint32_t dst = smb + LS_B + plane * 32768 + row * 1024 + swz16(c16, row) * 16;
        CP_ASYNC16(dst, src);
    }
    CP_COMMIT();
    CP_WAITG(0);
    __syncthreads();

    // ldmatrix lane geometry (verified)
    const int a_row = (lane & 7) + ((lane >> 3) & 1) * 8;
    const int a_cad = (lane >> 4) & 1;
    const int b_row = (lane & 7) + ((lane >> 4) & 1) * 8;
    const int b_cad = (lane >> 3) & 1;
    const int qrow  = lane >> 2;
    const int qcol  = (lane & 3) * 2;

    // register cell state (kq0 threads): [mt][half][unit]
    float cell[2][2][2];
    #pragma unroll
    for (int mt = 0; mt < 2; mt++)
        #pragma unroll
        for (int h2 = 0; h2 < 2; h2++)
            cell[mt][h2][0] = cell[mt][h2][1] = 0.f;

    // xz prefetch (kq==0 warps hold next step's accumulator seed)
    float pre[2][4][4];
    if (kq == 0) {
        #pragma unroll
        for (int mt = 0; mt < 2; mt++)
            #pragma unroll
            for (int h2 = 0; h2 < 2; h2++) {
                int b = mhalf * 32 + mt * 16 + qrow + h2 * 8;
                const float* xzp = &g_xz[dir][0][b][slice * 32];
                #pragma unroll
                for (int nt = 0; nt < 4; nt++) {
                    float2 v = *(const float2*)&xzp[nt * 8 + qcol];
                    pre[mt][nt][h2 * 2 + 0] = v.x;
                    pre[mt][nt][h2 * 2 + 1] = v.y;
                }
            }
    }

    // staging of group g (covers local k-chunks g*4..g*4+3, both planes, 32 rows)
    #define LSTM_STAGE_GROUP(hb, g) do {                                       \
        _Pragma("unroll")                                                      \
        for (int w = 0; w < 8; w++) {                                          \
            int row   = mhalf * 32 + ((w & 1) << 4) + (lane >> 1);             \
            int cl    = (g) * 4 + (((w >> 1) & 1) << 1) + (lane & 1);          \
            int plane = w >> 2;                                                \
            int gc16  = kq * 16 + cl;                                          \
            const __nv_bfloat16* src = (hb) +                                  \
                (size_t)plane * (BATCHN * HIDN) + (size_t)row * HIDN + gc16 * 8;\
            uint32_t dst = smb + LS_A + plane * 65536u + (uint32_t)row * 1024u \
                           + swz16(gc16, row) * 16u;                           \
            CP_ASYNC16(dst, src);                                              \
        }                                                                      \
        CP_COMMIT();                                                           \
    } while (0)

    // one k16 MMA step j (local), bf16x3
    #define LSTM_MMA_J(j) do {                                                 \
        int gc = kq * 16 + (j) * 2;                                            \
        uint32_t ah[2][4], al[2][4], bh[4][2], bl[4][2];                       \
        _Pragma("unroll")                                                      \
        for (int mt = 0; mt < 2; mt++) {                                       \
            int row = mhalf * 32 + mt * 16 + a_row;                            \
            uint32_t oh = smb + LS_A + row * 1024 + swz16(gc + a_cad, row) * 16;\
            LDSM_X4(ah[mt][0], ah[mt][1], ah[mt][2], ah[mt][3], oh);           \
            LDSM_X4(al[mt][0], al[mt][1], al[mt][2], al[mt][3], oh + 65536);   \
        }                                                                      \
        _Pragma("unroll")                                                      \
        for (int jn = 0; jn < 2; jn++) {                                       \
            int row = jn * 16 + b_row;                                         \
            uint32_t oh = smb + LS_B + row * 1024 + swz16(gc + b_cad, row) * 16;\
            LDSM_X4(bh[2*jn][0], bh[2*jn][1], bh[2*jn+1][0], bh[2*jn+1][1], oh);\
            LDSM_X4(bl[2*jn][0], bl[2*jn][1], bl[2*jn+1][0], bl[2*jn+1][1],    \
                    oh + 32768);                                               \
        }                                                                      \
        _Pragma("unroll")                                                      \
        for (int mt = 0; mt < 2; mt++)                                         \
            _Pragma("unroll")                                                  \
            for (int nt = 0; nt < 4; nt++) {                                   \
                MMA_BF16(c[mt][nt], ah[mt], bh[nt]);                           \
                MMA_BF16(c[mt][nt], ah[mt], bl[nt]);                           \
                MMA_BF16(c[mt][nt], al[mt], bh[nt]);                           \
            }                                                                  \
    } while (0)

    for (int s = 0; s < TLEN; s++) {
        // ---- stage this warp's A slice in 4 groups (issued back-to-back) ----
        if (s > 0) {
            const __nv_bfloat16* hb = &g_hb[dir][s & 1][0][0][0];
            LSTM_STAGE_GROUP(hb, 0);
            LSTM_STAGE_GROUP(hb, 1);
            LSTM_STAGE_GROUP(hb, 2);
            LSTM_STAGE_GROUP(hb, 3);
        }

        // ---- init accumulators: prefetched xz for kq==0, zero otherwise ----
        float c[2][4][4];
        if (kq == 0) {
            #pragma unroll
            for (int mt = 0; mt < 2; mt++)
                #pragma unroll
                for (int nt = 0; nt < 4; nt++)
                    #pragma unroll
                    for (int e = 0; e < 4; e++) c[mt][nt][e] = pre[mt][nt][e];
        } else {
            #pragma unroll
            for (int mt = 0; mt < 2; mt++)
                #pragma unroll
                for (int nt = 0; nt < 4; nt++)
                    #pragma unroll
                    for (int e = 0; e < 4; e++) c[mt][nt][e] = 0.f;
        }

        // ---- MMA, overlapped with staging arrival ----
        if (s > 0) {
            CP_WAITG(3);  LSTM_MMA_J(0);  LSTM_MMA_J(1);
            CP_WAITG(2);  LSTM_MMA_J(2);  LSTM_MMA_J(3);
            CP_WAITG(1);  LSTM_MMA_J(4);  LSTM_MMA_J(5);
            CP_WAITG(0);  LSTM_MMA_J(6);  LSTM_MMA_J(7);
        }

        // ---- single-round 3-buffer K reduction ----
        __syncthreads();
        if (kq != 0) {
            float* bp = (float*)(sm + LS_SPILL) + (kq - 1) * 2176; // [64][34]
            #pragma unroll
            for (int mt = 0; mt < 2; mt++)
                #pragma unroll
                for (int h2 = 0; h2 < 2; h2++) {
                    int r = mhalf * 32 + mt * 16 + qrow + h2 * 8;
                    #pragma unroll
                    for (int nt = 0; nt < 4; nt++) {
                        float2 v;
                        v.x = c[mt][nt][h2 * 2 + 0];
                        v.y = c[mt][nt][h2 * 2 + 1];
                        *(float2*)&bp[r * 34 + nt * 8 + qcol] = v;
                    }
                }
        }
        __syncthreads();

        // ---- kq0: reduce + gates in registers + h store ----
        if (kq == 0) {
            #pragma unroll
            for (int buf = 0; buf < 3; buf++) {
                const float* bp = (const float*)(sm + LS_SPILL) + buf * 2176;
                #pragma unroll
                for (int mt = 0; mt < 2; mt++)
                    #pragma unroll
                    for (int h2 = 0; h2 < 2; h2++) {
                        int r = mhalf * 32 + mt * 16 + qrow + h2 * 8;
                        #pragma unroll
                        for (int nt = 0; nt < 4; nt++) {
                            float2 v = *(const float2*)&bp[r * 34 + nt * 8 + qcol];
                            c[mt][nt][h2 * 2 + 0] += v.x;
                            c[mt][nt][h2 * 2 + 1] += v.y;
                        }
                    }
            }
            // gates: nt = gate index (i,f,g,o) for units qcol+u2
            const int pp = (s + 1) & 1;
            #pragma unroll
            for (int mt = 0; mt < 2; mt++)
                #pragma unroll
                for (int h2 = 0; h2 < 2; h2++) {
                    int b = mhalf * 32 + mt * 16 + qrow + h2 * 8;
                    float hh[2];
                    #pragma unroll
                    for (int u2 = 0; u2 < 2; u2++) {
                        int e = h2 * 2 + u2;
                        float gi = fsig(c[mt][0][e]);
                        float gf = fsig(c[mt][1][e]);
                        float gg = fmaxf(c[mt][2][e], 0.f);
                        float go = fsig(c[mt][3][e]);
                        float cv = gf * cell[mt][h2][u2] + gi * gg;
                        cell[mt][h2][u2] = cv;
                        hh[u2] = go * fmaxf(cv, 0.f);
                    }
                    __nv_bfloat162 vhi, vlo;
                    vhi.x = __float2bfloat16(hh[0]);
                    vhi.y = __float2bfloat16(hh[1]);
                    vlo.x = __float2bfloat16(hh[0] - __bfloat162float(vhi.x));
                    vlo.y = __float2bfloat16(hh[1] - __bfloat162float(vhi.y));
                    int kk = slice * 8 + qcol;
                    *(__nv_bfloat162*)&g_hb[dir][pp][0][b][kk] = vhi;
                    *(__nv_bfloat162*)&g_hb[dir][pp][1][b][kk] = vlo;
                    if (s == TLEN - 1) {
                        float2 vf; vf.x = hh[0]; vf.y = hh[1];
                        *(float2*)&g_h[dir][0][b][kk] = vf;
                    }
                }
            __threadfence();
            // prefetch next step's xz (post-fence; hidden under barrier)
            if (s < TLEN - 1) {
                #pragma unroll
                for (int mt = 0; mt < 2; mt++)
                    #pragma unroll
                    for (int h2 = 0; h2 < 2; h2++) {
                        int b = mhalf * 32 + mt * 16 + qrow + h2 * 8;
                        const float* xzp = &g_xz[dir][s + 1][b][slice * 32];
                        #pragma unroll
                        for (int nt = 0; nt < 4; nt++) {
                            float2 v = *(const float2*)&xzp[nt * 8 + qcol];
                            pre[mt][nt][h2 * 2 + 0] = v.x;
                            pre[mt][nt][h2 * 2 + 1] = v.y;
                        }
                    }
            }
        }

        if (s < TLEN - 1) {
            // per-direction single-poller barrier
            __syncthreads();
            if (tid == 0) {
                atomicAdd(&g_barc[dir], 1u);
                unsigned target = (unsigned)(s + 1) * 64u;
                volatile unsigned* vb = &g_barc[dir];
                while (*vb < target) { }
            }
            __syncthreads();
        }
    }
}

// ---------------------------------------------------------------------------
// Kernel 3: dense + softmax
// ---------------------------------------------------------------------------
__global__ __launch_bounds__(320) void dense_kernel(
    const float* __restrict__ Wd, const float* __restrict__ bd,
    float* __restrict__ out)
{
    const int b = blockIdx.x;
    const int w = threadIdx.x >> 5, lane = threadIdx.x & 31;
    __shared__ float logits[NCLSN];

    float sum = 0.f;
    for (int k = lane; k < 2 * HIDN; k += 32) {
        float hv = (k < HIDN) ? g_h[0][0][b][k] : g_h[1][0][b][k - HIDN];
        sum = fmaf(hv, Wd[k * NCLSN + w], sum);
    }
    #pragma unroll
    for (int off = 16; off > 0; off >>= 1)
        sum += __shfl_down_sync(0xffffffffu, sum, off);
    if (lane == 0) logits[w] = sum + bd[w];
    __syncthreads();

    if (threadIdx.x == 0) {
        float mx = logits[0];
        #pragma unroll
        for (int n = 1; n < NCLSN; n++) mx = fmaxf(mx, logits[n]);
        float es[NCLSN], ssum = 0.f;
        #pragma unroll
        for (int n = 0; n < NCLSN; n++) { es[n] = expf(logits[n] - mx); ssum += es[n]; }
        float inv = 1.f / ssum;
        #pragma unroll
        for (int n = 0; n < NCLSN; n++) out[b * NCLSN + n] = es[n] * inv;
    }
}

// ---------------------------------------------------------------------------
extern "C" void kernel_launch(void* const* d_in, const int* in_sizes, int n_in,
                              void* d_out, int out_size)
{
    const int*   x    = (const int*)  d_in[0];
    const float* emb  = (const float*)d_in[1];
    const float* Wx_f = (const float*)d_in[2];
    const float* Wh_f = (const float*)d_in[3];
    const float* b_f  = (const float*)d_in[4];
    const float* Wx_b = (const float*)d_in[5];
    const float* Wh_b = (const float*)d_in[6];
    const float* b_b  = (const float*)d_in[7];
    const float* Wd   = (const float*)d_in[8];
    const float* bd   = (const float*)d_in[9];
    float* out = (float*)d_out;

    (void)in_sizes; (void)n_in; (void)out_size;

    cudaFuncSetAttribute(gemm_mma,
                         cudaFuncAttributeMaxDynamicSharedMemorySize, GT_SMEM);
    cudaFuncSetAttribute(lstm_kernel,
                         cudaFuncAttributeMaxDynamicSharedMemorySize, LSTM_SMEM_BYTES);

    prep_w<<<dim3(G4, 2), KPAD>>>(Wx_f, b_f, Wx_b, b_b);
    prep_wh<<<dim3(G4, 2), HIDN>>>(Wh_f, Wh_b);
    prep_a<<<MROWS, KPAD>>>(x, emb);
    gemm_mma<<<2 * 128 * 16, 256, GT_SMEM>>>();
    lstm_kernel<<<128, 256, LSTM_SMEM_BYTES>>>();
    dense_kernel<<<BATCHN, 320>>>(Wd, bd, out);
}

// round 8
// speedup vs baseline: 1.1491x; 1.1491x over previous
#include <cuda_runtime.h>
#include <cuda_bf16.h>
#include <math.h>
#include <stdint.h>

#define VOCABN 50000
#define EMBN   300
#define KPAD   320     // EMB padded to 10 chunks of 32
#define TLEN   256
#define HIDN   512
#define G4     2048    // 4*HID
#define NCLSN  10
#define BATCHN 64
#define MROWS  (TLEN*BATCHN)

// ---------------------------------------------------------------------------
// Device scratch
// ---------------------------------------------------------------------------
__device__ __align__(256) float g_xz[2][TLEN][BATCHN][G4]; // permuted gate cols
__device__ __align__(256) float g_h[2][2][BATCHN][HIDN];   // fp32 h (final step, for dense)
__device__ unsigned g_bar;                                 // grid barrier counter

__device__ __align__(256) __nv_bfloat16 g_Ahi[(size_t)MROWS * KPAD];
__device__ __align__(256) __nv_bfloat16 g_Alo[(size_t)MROWS * KPAD];
__device__ __align__(256) __nv_bfloat16 g_Bhi[(size_t)2 * G4 * KPAD];
__device__ __align__(256) __nv_bfloat16 g_Blo[(size_t)2 * G4 * KPAD];
__device__ __align__(256) float g_biasp[2 * G4];

// recurrence operands: h as bf16 hi/lo planes, Wh^T (permuted) as bf16 hi/lo
__device__ __align__(256) __nv_bfloat16 g_hb[2][2][2][BATCHN][HIDN];   // [dir][pp][plane][b][k]
__device__ __align__(256) __nv_bfloat16 g_WhT[2][2][G4][HIDN];         // [dir][plane][p][k]

__device__ __forceinline__ int perm_src(int p) {
    return ((p >> 3) & 3) * HIDN + (p >> 5) * 8 + (p & 7);
}

__device__ __forceinline__ uint32_t smem_to_u32(const void* p) {
    uint32_t a;
    asm("{ .reg .u64 t; cvta.to.shared.u64 t, %1; cvt.u32.u64 %0, t; }"
        : "=r"(a) : "l"(p));
    return a;
}

// ---------------------------------------------------------------------------
// mma.sync / ldmatrix / cp.async helpers (baseline PTX, no 'a' features)
// ---------------------------------------------------------------------------
#define LDSM_X4(r0, r1, r2, r3, addr) \
    asm volatile("ldmatrix.sync.aligned.m8n8.x4.shared.b16 {%0,%1,%2,%3}, [%4];" \
        : "=r"(r0), "=r"(r1), "=r"(r2), "=r"(r3) : "r"(addr))

#define MMA_BF16(c, a, b) \
    asm volatile("mma.sync.aligned.m16n8k16.row.col.f32.bf16.bf16.f32 " \
        "{%0,%1,%2,%3}, {%4,%5,%6,%7}, {%8,%9}, {%0,%1,%2,%3};" \
        : "+f"((c)[0]), "+f"((c)[1]), "+f"((c)[2]), "+f"((c)[3]) \
        : "r"((a)[0]), "r"((a)[1]), "r"((a)[2]), "r"((a)[3]), \
          "r"((b)[0]), "r"((b)[1]))

#define CP_ASYNC16(dst, src) \
    asm volatile("cp.async.cg.shared.global [%0], [%1], 16;" \
        :: "r"(dst), "l"(src) : "memory")
#define CP_COMMIT() asm volatile("cp.async.commit_group;" ::: "memory")
#define CP_WAIT1()  asm volatile("cp.async.wait_group 1;" ::: "memory")
#define CP_WAIT0()  asm volatile("cp.async.wait_group 0;" ::: "memory")

// swizzle of a 16B-chunk index within a 1KB row (XOR low 3 bits with row&7)
__device__ __forceinline__ uint32_t swz16(uint32_t c16, uint32_t row) {
    return (c16 & ~7u) | ((c16 ^ row) & 7u);
}

__device__ __forceinline__ float fsig(float x) {
    return __fdividef(1.f, 1.f + __expf(-x));
}

// ---------------------------------------------------------------------------
// Prep kernels
// ---------------------------------------------------------------------------
__global__ __launch_bounds__(KPAD) void prep_w(
    const float* __restrict__ Wx_f, const float* __restrict__ b_f,
    const float* __restrict__ Wx_b, const float* __restrict__ b_b)
{
    int n = blockIdx.x, dir = blockIdx.y, k = threadIdx.x;
    if (n == 0 && dir == 0 && k == 0) g_bar = 0u;     // grid-barrier reset
    int src = perm_src(n);
    const float* Wx = dir ? Wx_b : Wx_f;
    float v = (k < EMBN) ? Wx[(size_t)k * G4 + src] : 0.f;
    __nv_bfloat16 hi = __float2bfloat16(v);
    __nv_bfloat16 lo = __float2bfloat16(v - __bfloat162float(hi));
    size_t idx = (size_t)(dir * G4 + n) * KPAD + k;
    g_Bhi[idx] = hi;
    g_Blo[idx] = lo;
    if (k == 0) g_biasp[dir * G4 + n] = (dir ? b_b : b_f)[src];
}

__global__ __launch_bounds__(KPAD) void prep_a(
    const int* __restrict__ x, const float* __restrict__ emb)
{
    int row = blockIdx.x;
    int t = row >> 6, b = row & 63;
    __shared__ int tok;
    if (threadIdx.x == 0) tok = x[b * TLEN + t];
    __syncthreads();
    int k = threadIdx.x;
    float v = (k < EMBN) ? emb[(size_t)tok * EMBN + k] : 0.f;
    __nv_bfloat16 hi = __float2bfloat16(v);
    __nv_bfloat16 lo = __float2bfloat16(v - __bfloat162float(hi));
    size_t idx = (size_t)row * KPAD + k;
    g_Ahi[idx] = hi;
    g_Alo[idx] = lo;
}

// Wh^T with gate-column permutation, bf16 hi/lo planes, k-contiguous rows
__global__ __launch_bounds__(HIDN) void prep_wh(
    const float* __restrict__ Wh_f, const float* __restrict__ Wh_b)
{
    int p = blockIdx.x, dir = blockIdx.y, k = threadIdx.x;
    int src = perm_src(p);
    float v = (dir ? Wh_b : Wh_f)[(size_t)k * G4 + src];
    __nv_bfloat16 hi = __float2bfloat16(v);
    __nv_bfloat16 lo = __float2bfloat16(v - __bfloat162float(hi));
    g_WhT[dir][0][p][k] = hi;
    g_WhT[dir][1][p][k] = lo;
}

// ---------------------------------------------------------------------------
// Tensor-core (mma.sync bf16x3) input projection.
// __launch_bounds__(256,2): verified win (regs 134->128, 2 CTAs/SM,
// tensor 56.9% -> 70.9%, 373us -> 301us).
// ---------------------------------------------------------------------------
#define GT_STAGE 32768
#define GT_SMEM  (2 * GT_STAGE)
#define NCHUNK   10

__global__ __launch_bounds__(256, 2) void gemm_mma()
{
    extern __shared__ char sm[];
    const uint32_t smb = smem_to_u32(sm);
    const int tid = threadIdx.x, wid = tid >> 5, lane = tid & 31;

    const int ntile = blockIdx.x & 15;
    const int mtile = (blockIdx.x >> 4) & 127;
    const int dir   = blockIdx.x >> 11;
    const int m0 = mtile * 128, n0 = ntile * 128;

    const int mwarp = (wid >> 2) * 64;
    const int nwarp = (wid & 3) * 32;

    const int crow = tid >> 3;
    const int cc   = tid & 7;
    const __nv_bfloat16* srcA_base = (cc < 4) ? g_Ahi : g_Alo;
    const __nv_bfloat16* srcB_base = (cc < 4) ? g_Bhi : g_Blo;
    const int ksub = (cc & 3) * 8;

    const int a_row = (lane & 7) + ((lane >> 3) & 1) * 8;
    const int a_cad = (lane >> 4) & 1;
    const int b_row = (lane & 7) + ((lane >> 4) & 1) * 8;
    const int b_cad = (lane >> 3) & 1;

    float c[4][4][4];
    #pragma unroll
    for (int i = 0; i < 4; i++)
        #pragma unroll
        for (int j = 0; j < 4; j++)
            #pragma unroll
            for (int e = 0; e < 4; e++) c[i][j][e] = 0.f;

    #define ISSUE_COPY(kc, stage) do {                                         \
        uint32_t sA = smb + (stage) * GT_STAGE;                                \
        uint32_t sB = sA + 16384;                                              \
        _Pragma("unroll")                                                      \
        for (int q = 0; q < 4; q++) {                                          \
            int row = crow + q * 32;                                           \
            uint32_t dof = (uint32_t)row * 128 + ((cc ^ (row & 7)) * 16);      \
            const __nv_bfloat16* sa = srcA_base +                              \
                (size_t)(m0 + row) * KPAD + (kc) * 32 + ksub;                  \
            const __nv_bfloat16* sb = srcB_base +                              \
                (size_t)(dir * G4 + n0 + row) * KPAD + (kc) * 32 + ksub;       \
            CP_ASYNC16(sA + dof, sa);                                          \
            CP_ASYNC16(sB + dof, sb);                                          \
        }                                                                      \
        CP_COMMIT();                                                           \
    } while (0)

    ISSUE_COPY(0, 0);

    #pragma unroll 1
    for (int kc = 0; kc < NCHUNK; kc++) {
        if (kc + 1 < NCHUNK) {
            ISSUE_COPY(kc + 1, (kc + 1) & 1);
            CP_WAIT1();
        } else {
            CP_WAIT0();
        }
        __syncthreads();

        const uint32_t sA = smb + (kc & 1) * GT_STAGE;
        const uint32_t sB = sA + 16384;

        #pragma unroll
        for (int ks = 0; ks < 2; ks++) {
            uint32_t ah[4][4], al[4][4], bh[4][2], bl[4][2];
            #pragma unroll
            for (int mt = 0; mt < 4; mt++) {
                int row = mwarp + mt * 16 + a_row;
                int swzr = row & 7;
                uint32_t oh = sA + (uint32_t)row * 128 +
                              (((ks * 2 + a_cad)     ^ swzr) * 16);
                uint32_t ol = sA + (uint32_t)row * 128 +
                              (((4 + ks * 2 + a_cad) ^ swzr) * 16);
                LDSM_X4(ah[mt][0], ah[mt][1], ah[mt][2], ah[mt][3], oh);
                LDSM_X4(al[mt][0], al[mt][1], al[mt][2], al[mt][3], ol);
            }
            #pragma unroll
            for (int j = 0; j < 2; j++) {
                int row = nwarp + j * 16 + b_row;
                int swzr = row & 7;
                uint32_t oh = sB + (uint32_t)row * 128 +
                              (((ks * 2 + b_cad)     ^ swzr) * 16);
                uint32_t ol = sB + (uint32_t)row * 128 +
                              (((4 + ks * 2 + b_cad) ^ swzr) * 16);
                LDSM_X4(bh[2*j][0], bh[2*j][1], bh[2*j+1][0], bh[2*j+1][1], oh);
                LDSM_X4(bl[2*j][0], bl[2*j][1], bl[2*j+1][0], bl[2*j+1][1], ol);
            }
            #pragma unroll
            for (int mt = 0; mt < 4; mt++)
                #pragma unroll
                for (int nt = 0; nt < 4; nt++) {
                    MMA_BF16(c[mt][nt], ah[mt], bh[nt]);
                    MMA_BF16(c[mt][nt], ah[mt], bl[nt]);
                    MMA_BF16(c[mt][nt], al[mt], bh[nt]);
                }
        }
        __syncthreads();
    }

    const int qrow = lane >> 2;
    const int qcol = (lane & 3) * 2;
    #pragma unroll
    for (int nt = 0; nt < 4; nt++) {
        int coll = nwarp + nt * 8 + qcol;
        int col  = n0 + coll;
        float2 bv = *(const float2*)&g_biasp[dir * G4 + col];
        #pragma unroll
        for (int mt = 0; mt < 4; mt++) {
            #pragma unroll
            for (int half = 0; half < 2; half++) {
                int g = m0 + mwarp + mt * 16 + qrow + half * 8;
                int t = g >> 6, b = g & 63;
                int tout = dir ? (TLEN - 1 - t) : t;
                float2 v;
                v.x = c[mt][nt][half * 2 + 0] + bv.x;
                v.y = c[mt][nt][half * 2 + 1] + bv.y;
                *(float2*)&g_xz[dir][tout][b][col] = v;
            }
        }
    }
}

// ---------------------------------------------------------------------------
// Kernel 2: persistent bidirectional LSTM recurrence — EXACT R4 structure
// (verified 1894us): 8 warps = 2(M:32 rows) x 4(K:128), bulk cp.async staging
// + single wait, 2-round K reduction, 512-thread gate stage, single-counter
// barrier. Only change vs R4: fast sigmoid (__expf) in the gate stage.
// ---------------------------------------------------------------------------
#define LS_A     0                   // A planes: 2 x 64KB (rows b, 1KB each)
#define LS_B     131072              // B planes: 2 x 32KB (rows n, 1KB each)
#define LS_SPILL 196608              // 4 bufs x [32][34] fp32 = 4 x 4352
#define LS_ZS    214016              // 64 x 33 fp32
#define LS_CS    222464              // 64 x 8 fp32
#define LSTM_SMEM_BYTES 224512

__global__ __launch_bounds__(256, 1) void lstm_kernel()
{
    extern __shared__ char sm[];
    const uint32_t smb = smem_to_u32(sm);
    float* zs = (float*)(sm + LS_ZS);
    float* cs = (float*)(sm + LS_CS);

    const int tid   = threadIdx.x;
    const int wid   = tid >> 5, lane = tid & 31;
    const int dir   = blockIdx.x >> 6;
    const int slice = blockIdx.x & 63;

    const int mhalf = wid & 1;        // M half: rows mhalf*32..+31
    const int kq    = wid >> 1;       // K quarter: k kq*128..+127

    // ---- one-time: load Wh^T slice (hi/lo) into smem, init cell state ----
    #pragma unroll
    for (int i = tid; i < 4096; i += 256) {       // 4096 16B chunks
        int plane = i >> 11;
        int row   = (i >> 6) & 31;
        int c16   = i & 63;
        const __nv_bfloat16* src = &g_WhT[dir][plane][slice * 32 + row][c16 * 8];
        uint32_t dst = smb + LS_B + plane * 32768 + row * 1024 + swz16(c16, row) * 16;
        CP_ASYNC16(dst, src);
    }
    CP_COMMIT();
    for (int i = tid; i < BATCHN * 8; i += 256) cs[i] = 0.f;
    CP_WAIT0();
    __syncthreads();

    // ldmatrix lane geometry (verified)
    const int a_row = (lane & 7) + ((lane >> 3) & 1) * 8;
    const int a_cad = (lane >> 4) & 1;
    const int b_row = (lane & 7) + ((lane >> 4) & 1) * 8;
    const int b_cad = (lane >> 3) & 1;
    const int qrow  = lane >> 2;
    const int qcol  = (lane & 3) * 2;
    const unsigned nb = gridDim.x;

    for (int s = 0; s < TLEN; s++) {
        // ---- stage this warp's A slice (32 rows x 128 k, hi+lo) ----
        if (s > 0) {
            const __nv_bfloat16* hb = &g_hb[dir][s & 1][0][0][0];
            #pragma unroll
            for (int q = 0; q < 32; q++) {
                int i = lane + q * 32;            // 1024 chunks per warp
                int plane = i >> 9;
                int rloc  = (i >> 4) & 31;
                int ccc   = i & 15;
                int row   = mhalf * 32 + rloc;
                int gc16  = kq * 16 + ccc;
                const __nv_bfloat16* src = hb +
                    (size_t)plane * (BATCHN * HIDN) + (size_t)row * HIDN + gc16 * 8;
                uint32_t dst = smb + LS_A + plane * 65536 + row * 1024 +
                               swz16(gc16, row) * 16;
                CP_ASYNC16(dst, src);
            }
            CP_COMMIT();
        }

        // ---- init accumulators from precomputed input projection ----
        float c[2][4][4];
        if (kq == 0) {
            #pragma unroll
            for (int mt = 0; mt < 2; mt++)
                #pragma unroll
                for (int half = 0; half < 2; half++) {
                    int b = mhalf * 32 + mt * 16 + qrow + half * 8;
                    const float* xzp = &g_xz[dir][s][b][slice * 32];
                    #pragma unroll
                    for (int nt = 0; nt < 4; nt++) {
                        float2 v = *(const float2*)&xzp[nt * 8 + qcol];
                        c[mt][nt][half * 2 + 0] = v.x;
                        c[mt][nt][half * 2 + 1] = v.y;
                    }
                }
        } else {
            #pragma unroll
            for (int mt = 0; mt < 2; mt++)
                #pragma unroll
                for (int nt = 0; nt < 4; nt++)
                    #pragma unroll
                    for (int e = 0; e < 4; e++) c[mt][nt][e] = 0.f;
        }

        // ---- MMA over this warp's K range ----
        if (s > 0) {
            CP_WAIT0();       // own slice only; no CTA sync needed
            #pragma unroll 2
            for (int j = 0; j < 8; j++) {
                int gc = kq * 16 + j * 2;
                uint32_t ah[2][4], al[2][4], bh[4][2], bl[4][2];
                #pragma unroll
                for (int mt = 0; mt < 2; mt++) {
                    int row = mhalf * 32 + mt * 16 + a_row;
                    uint32_t oh = smb + LS_A + row * 1024 + swz16(gc + a_cad, row) * 16;
                    LDSM_X4(ah[mt][0], ah[mt][1], ah[mt][2], ah[mt][3], oh);
                    LDSM_X4(al[mt][0], al[mt][1], al[mt][2], al[mt][3], oh + 65536);
                }
                #pragma unroll
                for (int jn = 0; jn < 2; jn++) {
                    int row = jn * 16 + b_row;
                    uint32_t oh = smb + LS_B + row * 1024 + swz16(gc + b_cad, row) * 16;
                    LDSM_X4(bh[2*jn][0], bh[2*jn][1], bh[2*jn+1][0], bh[2*jn+1][1], oh);
                    LDSM_X4(bl[2*jn][0], bl[2*jn][1], bl[2*jn+1][0], bl[2*jn+1][1],
                            oh + 32768);
                }
                #pragma unroll
                for (int mt = 0; mt < 2; mt++)
                    #pragma unroll
                    for (int nt = 0; nt < 4; nt++) {
                        MMA_BF16(c[mt][nt], ah[mt], bh[nt]);
                        MMA_BF16(c[mt][nt], ah[mt], bl[nt]);
                        MMA_BF16(c[mt][nt], al[mt], bh[nt]);
                    }
            }
        }

        // ---- cross-warp K reduction (2 rounds), final z -> zs ----
        #define PART_ST(bufidx) do {                                            \
            float* bp = (float*)(sm + LS_SPILL) + (bufidx) * 1088;              \
            _Pragma("unroll")                                                   \
            for (int mt = 0; mt < 2; mt++)                                      \
                _Pragma("unroll")                                               \
                for (int half = 0; half < 2; half++) {                          \
                    int r = mt * 16 + qrow + half * 8;                          \
                    _Pragma("unroll")                                           \
                    for (int nt = 0; nt < 4; nt++) {                            \
                        float2 v;                                               \
                        v.x = c[mt][nt][half * 2 + 0];                          \
                        v.y = c[mt][nt][half * 2 + 1];                          \
                        *(float2*)&bp[r * 34 + nt * 8 + qcol] = v;              \
                    }                                                           \
                }                                                               \
        } while (0)
        #define PART_ADD(bufidx) do {                                           \
            float* bp = (float*)(sm + LS_SPILL) + (bufidx) * 1088;              \
            _Pragma("unroll")                                                   \
            for (int mt = 0; mt < 2; mt++)                                      \
                _Pragma("unroll")                                               \
                for (int half = 0; half < 2; half++) {                          \
                    int r = mt * 16 + qrow + half * 8;                          \
                    _Pragma("unroll")                                           \
                    for (int nt = 0; nt < 4; nt++) {                            \
                        float2 v = *(const float2*)&bp[r * 34 + nt * 8 + qcol]; \
                        c[mt][nt][half * 2 + 0] += v.x;                         \
                        c[mt][nt][half * 2 + 1] += v.y;                         \
                    }                                                           \
                }                                                               \
        } while (0)

        __syncthreads();
        if (kq == 1 || kq == 3) PART_ST(mhalf * 2 + (kq >> 1));
        __syncthreads();
        if (kq == 0 || kq == 2) PART_ADD(mhalf * 2 + (kq >> 1));
        __syncthreads();
        if (kq == 2) PART_ST(mhalf * 2);
        __syncthreads();
        if (kq == 0) {
            PART_ADD(mhalf * 2);
            #pragma unroll
            for (int mt = 0; mt < 2; mt++)
                #pragma unroll
                for (int half = 0; half < 2; half++) {
                    int b = mhalf * 32 + mt * 16 + qrow + half * 8;
                    #pragma unroll
                    for (int nt = 0; nt < 4; nt++) {
                        zs[b * 33 + nt * 8 + qcol]     = c[mt][nt][half * 2 + 0];
                        zs[b * 33 + nt * 8 + qcol + 1] = c[mt][nt][half * 2 + 1];
                    }
                }
        }
        __syncthreads();

        // ---- gates (512-thread parallel stage, fast sigmoid) ----
        #pragma unroll
        for (int u = 0; u < 2; u++) {
            int p = tid + u * 256;
            int b = p >> 3, rr = p & 7;
            float zi = zs[b * 33 + rr];
            float zf = zs[b * 33 + 8 + rr];
            float zg = zs[b * 33 + 16 + rr];
            float zo = zs[b * 33 + 24 + rr];
            float gi = fsig(zi);
            float gf = fsig(zf);
            float gg = fmaxf(zg, 0.f);
            float go = fsig(zo);
            float cv = gf * cs[b * 8 + rr] + gi * gg;
            cs[b * 8 + rr] = cv;
            float hh = go * fmaxf(cv, 0.f);
            __nv_bfloat16 hi = __float2bfloat16(hh);
            __nv_bfloat16 lo = __float2bfloat16(hh - __bfloat162float(hi));
            int kk = slice * 8 + rr;
            int pp = (s + 1) & 1;
            g_hb[dir][pp][0][b][kk] = hi;
            g_hb[dir][pp][1][b][kk] = lo;
            if (s == TLEN - 1) g_h[dir][0][b][kk] = hh;
        }

        if (s < TLEN - 1) {
            __threadfence();
            __syncthreads();
            if (tid == 0) {
                atomicAdd(&g_bar, 1u);
                unsigned target = (unsigned)(s + 1) * nb;
                volatile unsigned* vb = &g_bar;
                while (*vb < target) { }
            }
            __syncthreads();
        }
    }
}

// ---------------------------------------------------------------------------
// Kernel 3: dense + softmax
// ---------------------------------------------------------------------------
__global__ __launch_bounds__(320) void dense_kernel(
    const float* __restrict__ Wd, const float* __restrict__ bd,
    float* __restrict__ out)
{
    const int b = blockIdx.x;
    const int w = threadIdx.x >> 5, lane = threadIdx.x & 31;
    __shared__ float logits[NCLSN];

    float sum = 0.f;
    for (int k = lane; k < 2 * HIDN; k += 32) {
        float hv = (k < HIDN) ? g_h[0][0][b][k] : g_h[1][0][b][k - HIDN];
        sum = fmaf(hv, Wd[k * NCLSN + w], sum);
    }
    #pragma unroll
    for (int off = 16; off > 0; off >>= 1)
        sum += __shfl_down_sync(0xffffffffu, sum, off);
    if (lane == 0) logits[w] = sum + bd[w];
    __syncthreads();

    if (threadIdx.x == 0) {
        float mx = logits[0];
        #pragma unroll
        for (int n = 1; n < NCLSN; n++) mx = fmaxf(mx, logits[n]);
        float es[NCLSN], ssum = 0.f;
        #pragma unroll
        for (int n = 0; n < NCLSN; n++) { es[n] = expf(logits[n] - mx); ssum += es[n]; }
        float inv = 1.f / ssum;
        #pragma unroll
        for (int n = 0; n < NCLSN; n++) out[b * NCLSN + n] = es[n] * inv;
    }
}

// ---------------------------------------------------------------------------
extern "C" void kernel_launch(void* const* d_in, const int* in_sizes, int n_in,
                              void* d_out, int out_size)
{
    const int*   x    = (const int*)  d_in[0];
    const float* emb  = (const float*)d_in[1];
    const float* Wx_f = (const float*)d_in[2];
    const float* Wh_f = (const float*)d_in[3];
    const float* b_f  = (const float*)d_in[4];
    const float* Wx_b = (const float*)d_in[5];
    const float* Wh_b = (const float*)d_in[6];
    const float* b_b  = (const float*)d_in[7];
    const float* Wd   = (const float*)d_in[8];
    const float* bd   = (const float*)d_in[9];
    float* out = (float*)d_out;

    (void)in_sizes; (void)n_in; (void)out_size;

    cudaFuncSetAttribute(gemm_mma,
                         cudaFuncAttributeMaxDynamicSharedMemorySize, GT_SMEM);
    cudaFuncSetAttribute(lstm_kernel,
                         cudaFuncAttributeMaxDynamicSharedMemorySize, LSTM_SMEM_BYTES);

    prep_w<<<dim3(G4, 2), KPAD>>>(Wx_f, b_f, Wx_b, b_b);
    prep_wh<<<dim3(G4, 2), HIDN>>>(Wh_f, Wh_b);
    prep_a<<<MROWS, KPAD>>>(x, emb);
    gemm_mma<<<2 * 128 * 16, 256, GT_SMEM>>>();
    lstm_kernel<<<128, 256, LSTM_SMEM_BYTES>>>();
    dense_kernel<<<BATCHN, 320>>>(Wd, bd, out);
}

// round 9
// speedup vs baseline: 1.2238x; 1.0650x over previous
#include <cuda_runtime.h>
#include <cuda_bf16.h>
#include <math.h>
#include <stdint.h>

#define VOCABN 50000
#define EMBN   300
#define KPAD   320     // EMB padded to 10 chunks of 32
#define TLEN   256
#define HIDN   512
#define G4     2048    // 4*HID
#define NCLSN  10
#define BATCHN 64
#define MROWS  (TLEN*BATCHN)

// ---------------------------------------------------------------------------
// Device scratch
// ---------------------------------------------------------------------------
__device__ __align__(256) float g_xz[2][TLEN][BATCHN][G4]; // permuted gate cols
__device__ __align__(256) float g_h[2][2][BATCHN][HIDN];   // fp32 h (final step, for dense)
__device__ unsigned g_bar;                                 // grid barrier counter

__device__ __align__(256) __nv_bfloat16 g_Ahi[(size_t)MROWS * KPAD];
__device__ __align__(256) __nv_bfloat16 g_Alo[(size_t)MROWS * KPAD];
__device__ __align__(256) __nv_bfloat16 g_Bhi[(size_t)2 * G4 * KPAD];
__device__ __align__(256) __nv_bfloat16 g_Blo[(size_t)2 * G4 * KPAD];
__device__ __align__(256) float g_biasp[2 * G4];

// recurrence operands: h as bf16 hi/lo planes, Wh^T (permuted) as bf16 hi/lo
__device__ __align__(256) __nv_bfloat16 g_hb[2][2][2][BATCHN][HIDN];   // [dir][pp][plane][b][k]
__device__ __align__(256) __nv_bfloat16 g_WhT[2][2][G4][HIDN];         // [dir][plane][p][k]

__device__ __forceinline__ int perm_src(int p) {
    return ((p >> 3) & 3) * HIDN + (p >> 5) * 8 + (p & 7);
}

__device__ __forceinline__ uint32_t smem_to_u32(const void* p) {
    uint32_t a;
    asm("{ .reg .u64 t; cvta.to.shared.u64 t, %1; cvt.u32.u64 %0, t; }"
        : "=r"(a) : "l"(p));
    return a;
}

// ---------------------------------------------------------------------------
// mma.sync / ldmatrix / cp.async helpers (baseline PTX, no 'a' features)
// ---------------------------------------------------------------------------
#define LDSM_X4(r0, r1, r2, r3, addr) \
    asm volatile("ldmatrix.sync.aligned.m8n8.x4.shared.b16 {%0,%1,%2,%3}, [%4];" \
        : "=r"(r0), "=r"(r1), "=r"(r2), "=r"(r3) : "r"(addr))

#define MMA_BF16(c, a, b) \
    asm volatile("mma.sync.aligned.m16n8k16.row.col.f32.bf16.bf16.f32 " \
        "{%0,%1,%2,%3}, {%4,%5,%6,%7}, {%8,%9}, {%0,%1,%2,%3};" \
        : "+f"((c)[0]), "+f"((c)[1]), "+f"((c)[2]), "+f"((c)[3]) \
        : "r"((a)[0]), "r"((a)[1]), "r"((a)[2]), "r"((a)[3]), \
          "r"((b)[0]), "r"((b)[1]))

#define CP_ASYNC16(dst, src) \
    asm volatile("cp.async.cg.shared.global [%0], [%1], 16;" \
        :: "r"(dst), "l"(src) : "memory")
#define CP_COMMIT() asm volatile("cp.async.commit_group;" ::: "memory")
#define CP_WAIT1()  asm volatile("cp.async.wait_group 1;" ::: "memory")
#define CP_WAIT0()  asm volatile("cp.async.wait_group 0;" ::: "memory")

// swizzle of a 16B-chunk index within a 1KB row (XOR low 3 bits with row&7)
__device__ __forceinline__ uint32_t swz16(uint32_t c16, uint32_t row) {
    return (c16 & ~7u) | ((c16 ^ row) & 7u);
}

__device__ __forceinline__ float fsig(float x) {
    return __fdividef(1.f, 1.f + __expf(-x));
}

// ---------------------------------------------------------------------------
// Prep kernels
// ---------------------------------------------------------------------------
__global__ __launch_bounds__(KPAD) void prep_w(
    const float* __restrict__ Wx_f, const float* __restrict__ b_f,
    const float* __restrict__ Wx_b, const float* __restrict__ b_b)
{
    int n = blockIdx.x, dir = blockIdx.y, k = threadIdx.x;
    if (n == 0 && dir == 0 && k == 0) g_bar = 0u;     // grid-barrier reset
    int src = perm_src(n);
    const float* Wx = dir ? Wx_b : Wx_f;
    float v = (k < EMBN) ? Wx[(size_t)k * G4 + src] : 0.f;
    __nv_bfloat16 hi = __float2bfloat16(v);
    __nv_bfloat16 lo = __float2bfloat16(v - __bfloat162float(hi));
    size_t idx = (size_t)(dir * G4 + n) * KPAD + k;
    g_Bhi[idx] = hi;
    g_Blo[idx] = lo;
    if (k == 0) g_biasp[dir * G4 + n] = (dir ? b_b : b_f)[src];
}

__global__ __launch_bounds__(KPAD) void prep_a(
    const int* __restrict__ x, const float* __restrict__ emb)
{
    int row = blockIdx.x;
    int t = row >> 6, b = row & 63;
    __shared__ int tok;
    if (threadIdx.x == 0) tok = x[b * TLEN + t];
    __syncthreads();
    int k = threadIdx.x;
    float v = (k < EMBN) ? emb[(size_t)tok * EMBN + k] : 0.f;
    __nv_bfloat16 hi = __float2bfloat16(v);
    __nv_bfloat16 lo = __float2bfloat16(v - __bfloat162float(hi));
    size_t idx = (size_t)row * KPAD + k;
    g_Ahi[idx] = hi;
    g_Alo[idx] = lo;
}

// Wh^T with gate-column permutation, bf16 hi/lo planes, k-contiguous rows
__global__ __launch_bounds__(HIDN) void prep_wh(
    const float* __restrict__ Wh_f, const float* __restrict__ Wh_b)
{
    int p = blockIdx.x, dir = blockIdx.y, k = threadIdx.x;
    int src = perm_src(p);
    float v = (dir ? Wh_b : Wh_f)[(size_t)k * G4 + src];
    __nv_bfloat16 hi = __float2bfloat16(v);
    __nv_bfloat16 lo = __float2bfloat16(v - __bfloat162float(hi));
    g_WhT[dir][0][p][k] = hi;
    g_WhT[dir][1][p][k] = lo;
}

// ---------------------------------------------------------------------------
// Tensor-core (mma.sync bf16x3) input projection (unchanged, verified 298us)
// ---------------------------------------------------------------------------
#define GT_STAGE 32768
#define GT_SMEM  (2 * GT_STAGE)
#define NCHUNK   10

__global__ __launch_bounds__(256, 2) void gemm_mma()
{
    extern __shared__ char sm[];
    const uint32_t smb = smem_to_u32(sm);
    const int tid = threadIdx.x, wid = tid >> 5, lane = tid & 31;

    const int ntile = blockIdx.x & 15;
    const int mtile = (blockIdx.x >> 4) & 127;
    const int dir   = blockIdx.x >> 11;
    const int m0 = mtile * 128, n0 = ntile * 128;

    const int mwarp = (wid >> 2) * 64;
    const int nwarp = (wid & 3) * 32;

    const int crow = tid >> 3;
    const int cc   = tid & 7;
    const __nv_bfloat16* srcA_base = (cc < 4) ? g_Ahi : g_Alo;
    const __nv_bfloat16* srcB_base = (cc < 4) ? g_Bhi : g_Blo;
    const int ksub = (cc & 3) * 8;

    const int a_row = (lane & 7) + ((lane >> 3) & 1) * 8;
    const int a_cad = (lane >> 4) & 1;
    const int b_row = (lane & 7) + ((lane >> 4) & 1) * 8;
    const int b_cad = (lane >> 3) & 1;

    float c[4][4][4];
    #pragma unroll
    for (int i = 0; i < 4; i++)
        #pragma unroll
        for (int j = 0; j < 4; j++)
            #pragma unroll
            for (int e = 0; e < 4; e++) c[i][j][e] = 0.f;

    #define ISSUE_COPY(kc, stage) do {                                         \
        uint32_t sA = smb + (stage) * GT_STAGE;                                \
        uint32_t sB = sA + 16384;                                              \
        _Pragma("unroll")                                                      \
        for (int q = 0; q < 4; q++) {                                          \
            int row = crow + q * 32;                                           \
            uint32_t dof = (uint32_t)row * 128 + ((cc ^ (row & 7)) * 16);      \
            const __nv_bfloat16* sa = srcA_base +                              \
                (size_t)(m0 + row) * KPAD + (kc) * 32 + ksub;                  \
            const __nv_bfloat16* sb = srcB_base +                              \
                (size_t)(dir * G4 + n0 + row) * KPAD + (kc) * 32 + ksub;       \
            CP_ASYNC16(sA + dof, sa);                                          \
            CP_ASYNC16(sB + dof, sb);                                          \
        }                                                                      \
        CP_COMMIT();                                                           \
    } while (0)

    ISSUE_COPY(0, 0);

    #pragma unroll 1
    for (int kc = 0; kc < NCHUNK; kc++) {
        if (kc + 1 < NCHUNK) {
            ISSUE_COPY(kc + 1, (kc + 1) & 1);
            CP_WAIT1();
        } else {
            CP_WAIT0();
        }
        __syncthreads();

        const uint32_t sA = smb + (kc & 1) * GT_STAGE;
        const uint32_t sB = sA + 16384;

        #pragma unroll
        for (int ks = 0; ks < 2; ks++) {
            uint32_t ah[4][4], al[4][4], bh[4][2], bl[4][2];
            #pragma unroll
            for (int mt = 0; mt < 4; mt++) {
                int row = mwarp + mt * 16 + a_row;
                int swzr = row & 7;
                uint32_t oh = sA + (uint32_t)row * 128 +
                              (((ks * 2 + a_cad)     ^ swzr) * 16);
                uint32_t ol = sA + (uint32_t)row * 128 +
                              (((4 + ks * 2 + a_cad) ^ swzr) * 16);
                LDSM_X4(ah[mt][0], ah[mt][1], ah[mt][2], ah[mt][3], oh);
                LDSM_X4(al[mt][0], al[mt][1], al[mt][2], al[mt][3], ol);
            }
            #pragma unroll
            for (int j = 0; j < 2; j++) {
                int row = nwarp + j * 16 + b_row;
                int swzr = row & 7;
                uint32_t oh = sB + (uint32_t)row * 128 +
                              (((ks * 2 + b_cad)     ^ swzr) * 16);
                uint32_t ol = sB + (uint32_t)row * 128 +
                              (((4 + ks * 2 + b_cad) ^ swzr) * 16);
                LDSM_X4(bh[2*j][0], bh[2*j][1], bh[2*j+1][0], bh[2*j+1][1], oh);
                LDSM_X4(bl[2*j][0], bl[2*j][1], bl[2*j+1][0], bl[2*j+1][1], ol);
            }
            #pragma unroll
            for (int mt = 0; mt < 4; mt++)
                #pragma unroll
                for (int nt = 0; nt < 4; nt++) {
                    MMA_BF16(c[mt][nt], ah[mt], bh[nt]);
                    MMA_BF16(c[mt][nt], ah[mt], bl[nt]);
                    MMA_BF16(c[mt][nt], al[mt], bh[nt]);
                }
        }
        __syncthreads();
    }

    const int qrow = lane >> 2;
    const int qcol = (lane & 3) * 2;
    #pragma unroll
    for (int nt = 0; nt < 4; nt++) {
        int coll = nwarp + nt * 8 + qcol;
        int col  = n0 + coll;
        float2 bv = *(const float2*)&g_biasp[dir * G4 + col];
        #pragma unroll
        for (int mt = 0; mt < 4; mt++) {
            #pragma unroll
            for (int half = 0; half < 2; half++) {
                int g = m0 + mwarp + mt * 16 + qrow + half * 8;
                int t = g >> 6, b = g & 63;
                int tout = dir ? (TLEN - 1 - t) : t;
                float2 v;
                v.x = c[mt][nt][half * 2 + 0] + bv.x;
                v.y = c[mt][nt][half * 2 + 1] + bv.y;
                *(float2*)&g_xz[dir][tout][b][col] = v;
            }
        }
    }
}

// ---------------------------------------------------------------------------
// Kernel 2: persistent bidirectional LSTM recurrence, mma.sync bf16x3.
// 8 warps = 2(M:32 rows) x 4(K:128). Changes vs R8 (verified 1765us):
//  1. plane-split staging: hi plane committed first; phase-A MMAs
//     (Ahi*Bhi + Ahi*Blo) run under WAIT1 while lo plane lands; phase B
//     (Alo*Bhi) after WAIT0. Bulk issue preserved (2 groups only).
//  2. single-round 4-buffer reduction: all kq warps store partials once,
//     ONE sync, 512-thread gate stage sums 4 partials directly.
//     Cell state in registers (fixed tid<->(b,unit) map). 5 syncs -> 2.
//  3. release/acquire barrier (no __threadfence L1 flush).
// ---------------------------------------------------------------------------
#define LS_A     0                   // A planes: 2 x 64KB (rows b, 1KB each)
#define LS_B     131072              // B planes: 2 x 32KB (rows n, 1KB each)
#define LS_SPILL 196608              // 4 bufs x [64][34] fp32 = 4 x 8704
#define LSTM_SMEM_BYTES (196608 + 4 * 8704)   // 231424

__global__ __launch_bounds__(256, 1) void lstm_kernel()
{
    extern __shared__ char sm[];
    const uint32_t smb = smem_to_u32(sm);
    float* spill = (float*)(sm + LS_SPILL);

    const int tid   = threadIdx.x;
    const int wid   = tid >> 5, lane = tid & 31;
    const int dir   = blockIdx.x >> 6;
    const int slice = blockIdx.x & 63;

    const int mhalf = wid & 1;        // M half: rows mhalf*32..+31
    const int kq    = wid >> 1;       // K quarter: k kq*128..+127

    // ---- one-time: load Wh^T slice (hi/lo) into smem ----
    #pragma unroll
    for (int i = tid; i < 4096; i += 256) {       // 4096 16B chunks
        int plane = i >> 11;
        int row   = (i >> 6) & 31;
        int c16   = i & 63;
        const __nv_bfloat16* src = &g_WhT[dir][plane][slice * 32 + row][c16 * 8];
        uint32_t dst = smb + LS_B + plane * 32768 + row * 1024 + swz16(c16, row) * 16;
        CP_ASYNC16(dst, src);
    }
    CP_COMMIT();
    CP_WAIT0();
    __syncthreads();

    // ldmatrix lane geometry (verified)
    const int a_row = (lane & 7) + ((lane >> 3) & 1) * 8;
    const int a_cad = (lane >> 4) & 1;
    const int b_row = (lane & 7) + ((lane >> 4) & 1) * 8;
    const int b_cad = (lane >> 3) & 1;
    const int qrow  = lane >> 2;
    const int qcol  = (lane & 3) * 2;
    const unsigned nb = gridDim.x;

    // register cell state: u-loop pair (tid, tid+256) -> fixed (b, rr)
    float cell[2] = {0.f, 0.f};

    for (int s = 0; s < TLEN; s++) {
        // ---- stage this warp's A slice: hi plane group, then lo plane ----
        if (s > 0) {
            const __nv_bfloat16* hb = &g_hb[dir][s & 1][0][0][0];
            #pragma unroll
            for (int q = 0; q < 16; q++) {        // plane 0 (hi)
                int i = lane + q * 32;
                int rloc  = (i >> 4) & 31;
                int ccc   = i & 15;
                int row   = mhalf * 32 + rloc;
                int gc16  = kq * 16 + ccc;
                const __nv_bfloat16* src = hb + (size_t)row * HIDN + gc16 * 8;
                uint32_t dst = smb + LS_A + row * 1024 + swz16(gc16, row) * 16;
                CP_ASYNC16(dst, src);
            }
            CP_COMMIT();
            #pragma unroll
            for (int q = 0; q < 16; q++) {        // plane 1 (lo)
                int i = lane + q * 32;
                int rloc  = (i >> 4) & 31;
                int ccc   = i & 15;
                int row   = mhalf * 32 + rloc;
                int gc16  = kq * 16 + ccc;
                const __nv_bfloat16* src = hb + (size_t)(BATCHN * HIDN)
                                             + (size_t)row * HIDN + gc16 * 8;
                uint32_t dst = smb + LS_A + 65536 + row * 1024 +
                               swz16(gc16, row) * 16;
                CP_ASYNC16(dst, src);
            }
            CP_COMMIT();
        }

        // ---- init accumulators from precomputed input projection ----
        float c[2][4][4];
        if (kq == 0) {
            #pragma unroll
            for (int mt = 0; mt < 2; mt++)
                #pragma unroll
                for (int half = 0; half < 2; half++) {
                    int b = mhalf * 32 + mt * 16 + qrow + half * 8;
                    const float* xzp = &g_xz[dir][s][b][slice * 32];
                    #pragma unroll
                    for (int nt = 0; nt < 4; nt++) {
                        float2 v = *(const float2*)&xzp[nt * 8 + qcol];
                        c[mt][nt][half * 2 + 0] = v.x;
                        c[mt][nt][half * 2 + 1] = v.y;
                    }
                }
        } else {
            #pragma unroll
            for (int mt = 0; mt < 2; mt++)
                #pragma unroll
                for (int nt = 0; nt < 4; nt++)
                    #pragma unroll
                    for (int e = 0; e < 4; e++) c[mt][nt][e] = 0.f;
        }

        // ---- MMA: phase A (hi plane) under WAIT1, phase B after WAIT0 ----
        if (s > 0) {
            CP_WAIT1();
            #pragma unroll 2
            for (int j = 0; j < 8; j++) {
                int gc = kq * 16 + j * 2;
                uint32_t ah[2][4], bh[4][2], bl[4][2];
                #pragma unroll
                for (int mt = 0; mt < 2; mt++) {
                    int row = mhalf * 32 + mt * 16 + a_row;
                    uint32_t oh = smb + LS_A + row * 1024 + swz16(gc + a_cad, row) * 16;
                    LDSM_X4(ah[mt][0], ah[mt][1], ah[mt][2], ah[mt][3], oh);
                }
                #pragma unroll
                for (int jn = 0; jn < 2; jn++) {
                    int row = jn * 16 + b_row;
                    uint32_t oh = smb + LS_B + row * 1024 + swz16(gc + b_cad, row) * 16;
                    LDSM_X4(bh[2*jn][0], bh[2*jn][1], bh[2*jn+1][0], bh[2*jn+1][1], oh);
                    LDSM_X4(bl[2*jn][0], bl[2*jn][1], bl[2*jn+1][0], bl[2*jn+1][1],
                            oh + 32768);
                }
                #pragma unroll
                for (int mt = 0; mt < 2; mt++)
                    #pragma unroll
                    for (int nt = 0; nt < 4; nt++) {
                        MMA_BF16(c[mt][nt], ah[mt], bh[nt]);
                        MMA_BF16(c[mt][nt], ah[mt], bl[nt]);
                    }
            }
            CP_WAIT0();
            #pragma unroll 2
            for (int j = 0; j < 8; j++) {
                int gc = kq * 16 + j * 2;
                uint32_t al[2][4], bh[4][2];
                #pragma unroll
                for (int mt = 0; mt < 2; mt++) {
                    int row = mhalf * 32 + mt * 16 + a_row;
                    uint32_t ol = smb + LS_A + 65536 + row * 1024 +
                                  swz16(gc + a_cad, row) * 16;
                    LDSM_X4(al[mt][0], al[mt][1], al[mt][2], al[mt][3], ol);
                }
                #pragma unroll
                for (int jn = 0; jn < 2; jn++) {
                    int row = jn * 16 + b_row;
                    uint32_t oh = smb + LS_B + row * 1024 + swz16(gc + b_cad, row) * 16;
                    LDSM_X4(bh[2*jn][0], bh[2*jn][1], bh[2*jn+1][0], bh[2*jn+1][1], oh);
                }
                #pragma unroll
                for (int mt = 0; mt < 2; mt++)
                    #pragma unroll
                    for (int nt = 0; nt < 4; nt++)
                        MMA_BF16(c[mt][nt], al[mt], bh[nt]);
            }
        }

        // ---- single-round: every warp stores partials to its kq buffer ----
        __syncthreads();
        {
            float* bp = spill + kq * 2176;   // [64][34]
            #pragma unroll
            for (int mt = 0; mt < 2; mt++)
                #pragma unroll
                for (int half = 0; half < 2; half++) {
                    int r = mhalf * 32 + mt * 16 + qrow + half * 8;
                    #pragma unroll
                    for (int nt = 0; nt < 4; nt++) {
                        float2 v;
                        v.x = c[mt][nt][half * 2 + 0];
                        v.y = c[mt][nt][half * 2 + 1];
                        *(float2*)&bp[r * 34 + nt * 8 + qcol] = v;
                    }
                }
        }
        __syncthreads();

        // ---- gates: 512 (b,rr) pairs, sum 4 partials per gate ----
        #pragma unroll
        for (int u = 0; u < 2; u++) {
            int p = tid + u * 256;
            int b = p >> 3, rr = p & 7;
            float z[4];
            #pragma unroll
            for (int g = 0; g < 4; g++) {
                z[g] = spill[b * 34 + g * 8 + rr]
                     + spill[2176 + b * 34 + g * 8 + rr]
                     + spill[4352 + b * 34 + g * 8 + rr]
                     + spill[6528 + b * 34 + g * 8 + rr];
            }
            float gi = fsig(z[0]);
            float gf = fsig(z[1]);
            float gg = fmaxf(z[2], 0.f);
            float go = fsig(z[3]);
            float cv = gf * cell[u] + gi * gg;
            cell[u] = cv;
            float hh = go * fmaxf(cv, 0.f);
            __nv_bfloat16 hi = __float2bfloat16(hh);
            __nv_bfloat16 lo = __float2bfloat16(hh - __bfloat162float(hi));
            int kk = slice * 8 + rr;
            int pp = (s + 1) & 1;
            g_hb[dir][pp][0][b][kk] = hi;
            g_hb[dir][pp][1][b][kk] = lo;
            if (s == TLEN - 1) g_h[dir][0][b][kk] = hh;
        }

        if (s < TLEN - 1) {
            // release/acquire grid barrier (no L1-flushing threadfence)
            __syncthreads();
            if (tid == 0) {
                asm volatile("red.release.gpu.global.add.u32 [%0], %1;"
                             :: "l"(&g_bar), "r"(1u) : "memory");
                unsigned target = (unsigned)(s + 1) * nb;
                unsigned v;
                do {
                    asm volatile("ld.acquire.gpu.global.u32 %0, [%1];"
                                 : "=r"(v) : "l"(&g_bar) : "memory");
                } while (v < target);
            }
            __syncthreads();
        }
    }
}

// ---------------------------------------------------------------------------
// Kernel 3: dense + softmax
// ---------------------------------------------------------------------------
__global__ __launch_bounds__(320) void dense_kernel(
    const float* __restrict__ Wd, const float* __restrict__ bd,
    float* __restrict__ out)
{
    const int b = blockIdx.x;
    const int w = threadIdx.x >> 5, lane = threadIdx.x & 31;
    __shared__ float logits[NCLSN];

    float sum = 0.f;
    for (int k = lane; k < 2 * HIDN; k += 32) {
        float hv = (k < HIDN) ? g_h[0][0][b][k] : g_h[1][0][b][k - HIDN];
        sum = fmaf(hv, Wd[k * NCLSN + w], sum);
    }
    #pragma unroll
    for (int off = 16; off > 0; off >>= 1)
        sum += __shfl_down_sync(0xffffffffu, sum, off);
    if (lane == 0) logits[w] = sum + bd[w];
    __syncthreads();

    if (threadIdx.x == 0) {
        float mx = logits[0];
        #pragma unroll
        for (int n = 1; n < NCLSN; n++) mx = fmaxf(mx, logits[n]);
        float es[NCLSN], ssum = 0.f;
        #pragma unroll
        for (int n = 0; n < NCLSN; n++) { es[n] = expf(logits[n] - mx); ssum += es[n]; }
        float inv = 1.f / ssum;
        #pragma unroll
        for (int n = 0; n < NCLSN; n++) out[b * NCLSN + n] = es[n] * inv;
    }
}

// ---------------------------------------------------------------------------
extern "C" void kernel_launch(void* const* d_in, const int* in_sizes, int n_in,
                              void* d_out, int out_size)
{
    const int*   x    = (const int*)  d_in[0];
    const float* emb  = (const float*)d_in[1];
    const float* Wx_f = (const float*)d_in[2];
    const float* Wh_f = (const float*)d_in[3];
    const float* b_f  = (const float*)d_in[4];
    const float* Wx_b = (const float*)d_in[5];
    const float* Wh_b = (const float*)d_in[6];
    const float* b_b  = (const float*)d_in[7];
    const float* Wd   = (const float*)d_in[8];
    const float* bd   = (const float*)d_in[9];
    float* out = (float*)d_out;

    (void)in_sizes; (void)n_in; (void)out_size;

    cudaFuncSetAttribute(gemm_mma,
                         cudaFuncAttributeMaxDynamicSharedMemorySize, GT_SMEM);
    cudaFuncSetAttribute(lstm_kernel,
                         cudaFuncAttributeMaxDynamicSharedMemorySize, LSTM_SMEM_BYTES);

    prep_w<<<dim3(G4, 2), KPAD>>>(Wx_f, b_f, Wx_b, b_b);
    prep_wh<<<dim3(G4, 2), HIDN>>>(Wh_f, Wh_b);
    prep_a<<<MROWS, KPAD>>>(x, emb);
    gemm_mma<<<2 * 128 * 16, 256, GT_SMEM>>>();
    lstm_kernel<<<128, 256, LSTM_SMEM_BYTES>>>();
    dense_kernel<<<BATCHN, 320>>>(Wd, bd, out);
}